// round 14
// baseline (speedup 1.0000x reference)
#include <cuda_runtime.h>
#include <cuda_fp16.h>
#include <cstdint>

#define BB 16
#define NN 4096

// ---------------- persistent device scratch --------------------------------
__device__ float4 d_x4[BB * NN];
__device__ int    d_idx[BB * NN * 32];
__device__ __half d_w2h[128 * 64];      // [n=128][k=64]
__device__ __half d_w3h[1024 * 128];    // [n=1024][k=128]
__device__ float  d_g[BB * 1024];
__device__ float  d_f1[BB * 512];
__device__ float  d_tm[BB * 9];

// ---------------- smem map (bytes) -----------------------------------------
#define SM_WB0   0        /* W3 chunk buf0: 128 x 272 = 34816 */
#define SM_WB1   34816    /* W3 chunk buf1 */
#define SM_WB2   69632    /* W2: 128 x 144 = 18432 */
#define SM_CMAX  88064    /* 8 warps x 512 u32 (half2 col-max) = 16384 */
#define SM_X0    104448   /* 256 x float4 = 4096 */
#define SM_CONST 108544   /* w1(192f) b1(64f) b2(128f) = 1536, pad 2048 */
#define SM_TOT   110592

// ---------------- helpers ---------------------------------------------------
__device__ __forceinline__ uint32_t smem_u32(const void* p) {
    uint32_t a;
    asm("{ .reg .u64 t; cvta.to.shared.u64 t, %1; cvt.u32.u64 %0, t; }"
        : "=r"(a) : "l"(p));
    return a;
}
__device__ __forceinline__ void ldsm4(uint32_t& r0, uint32_t& r1,
                                      uint32_t& r2, uint32_t& r3, uint32_t a) {
    asm volatile("ldmatrix.sync.aligned.m8n8.x4.shared.b16 {%0,%1,%2,%3}, [%4];"
                 : "=r"(r0), "=r"(r1), "=r"(r2), "=r"(r3) : "r"(a));
}
__device__ __forceinline__ void mma16816h(uint32_t* c, const uint32_t* a,
                                          uint32_t b0, uint32_t b1) {
    asm volatile("mma.sync.aligned.m16n8k16.row.col.f16.f16.f16.f16 "
                 "{%0,%1}, {%2,%3,%4,%5}, {%6,%7}, {%0,%1};"
                 : "+r"(c[0]), "+r"(c[1])
                 : "r"(a[0]), "r"(a[1]), "r"(a[2]), "r"(a[3]), "r"(b0), "r"(b1));
}
__device__ __forceinline__ void cpasync16(uint32_t dst, const void* src) {
    asm volatile("cp.async.cg.shared.global [%0], [%1], 16;" :: "r"(dst), "l"(src));
}
__device__ __forceinline__ void cpcommit() { asm volatile("cp.async.commit_group;"); }
__device__ __forceinline__ void cpwait1()  { asm volatile("cp.async.wait_group 1;"); }

// relu(W1[o..o+1] . e + b1) packed as half2 — feeds A-fragments directly
__device__ __forceinline__ uint32_t h1pair(const float* C, float4 e, int o) {
    float v0 = fmaxf(fmaf(e.x, C[3 * o + 0], fmaf(e.y, C[3 * o + 1],
                     fmaf(e.z, C[3 * o + 2], C[192 + o]))), 0.f);
    float v1 = fmaxf(fmaf(e.x, C[3 * o + 3], fmaf(e.y, C[3 * o + 4],
                     fmaf(e.z, C[3 * o + 5], C[192 + o + 1]))), 0.f);
    __half2 h = __floats2half2_rn(v0, v1);
    return *(uint32_t*)&h;
}

// ---------------- prep ------------------------------------------------------
__global__ void prep_x_kernel(const float* __restrict__ x) {
    int id = blockIdx.x * blockDim.x + threadIdx.x;
    if (id >= BB * NN) return;
    int b = id >> 12, j = id & (NN - 1);
    const float* xb = x + (size_t)b * 3 * NN;
    float a0 = xb[j], a1 = xb[NN + j], a2 = xb[2 * NN + j];
    d_x4[id] = make_float4(a0, a1, a2, a0 * a0 + a1 * a1 + a2 * a2);
}
__global__ void prep_wg_kernel(const float* __restrict__ w2,
                               const float* __restrict__ w3) {
    int id = blockIdx.x * blockDim.x + threadIdx.x;
    if (id < 1024 * 128) d_w3h[id] = __float2half(w3[id]);
    if (id < 128 * 64)   d_w2h[id] = __float2half(w2[id]);
    if (id < BB * 1024)  d_g[id] = 0.f;
}

// ---------------- kNN: warp handles 4 points, exact two-pass ----------------
// One candidate load serves 4 points; per-point threshold + insertion logic
// identical to the single-point version (neighbor sets bit-identical).
__global__ void __launch_bounds__(256) knn_kernel() {
    const unsigned F = 0xffffffffu;
    int warp = threadIdx.x >> 5, lane = threadIdx.x & 31;
    int b = blockIdx.x >> 7;                          // 128 blocks per batch
    int i0 = ((blockIdx.x & 127) << 5) + warp * 4;    // 32 points per block
    const float4* xb = d_x4 + b * NN;
    float4 xA = xb[i0], xB = xb[i0 + 1], xC = xb[i0 + 2], xD = xb[i0 + 3];
    float txA = 2.f * xA.x, tyA = 2.f * xA.y, tzA = 2.f * xA.z;
    float txB = 2.f * xB.x, tyB = 2.f * xB.y, tzB = 2.f * xB.z;
    float txC = 2.f * xC.x, tyC = 2.f * xC.y, tzC = 2.f * xC.z;
    float txD = 2.f * xD.x, tyD = 2.f * xD.y, tzD = 2.f * xD.z;

    // ---- pass 1: per-lane maxes for 4 points (shared loads) ----
    float lmA = -3.4e38f, lmB = -3.4e38f, lmC = -3.4e38f, lmD = -3.4e38f;
    #pragma unroll 4
    for (int jb = 0; jb < NN; jb += 32) {
        float4 p = xb[jb + lane];
        lmA = fmaxf(lmA, fmaf(txA, p.x, fmaf(tyA, p.y, fmaf(tzA, p.z, -p.w))));
        lmB = fmaxf(lmB, fmaf(txB, p.x, fmaf(tyB, p.y, fmaf(tzB, p.z, -p.w))));
        lmC = fmaxf(lmC, fmaf(txC, p.x, fmaf(tyC, p.y, fmaf(tzC, p.z, -p.w))));
        lmD = fmaxf(lmD, fmaf(txD, p.x, fmaf(tyD, p.y, fmaf(tzD, p.z, -p.w))));
    }
    float tsA = lmA, tsB = lmB, tsC = lmC, tsD = lmD;
    #pragma unroll
    for (int off = 16; off; off >>= 1) {
        tsA = fminf(tsA, __shfl_xor_sync(F, tsA, off));
        tsB = fminf(tsB, __shfl_xor_sync(F, tsB, off));
        tsC = fminf(tsC, __shfl_xor_sync(F, tsC, off));
        tsD = fminf(tsD, __shfl_xor_sync(F, tsD, off));
    }

    // ---- pass 2: collect candidates >= t* per point ----
    float bvA = -3.4e38f, bvB = -3.4e38f, bvC = -3.4e38f, bvD = -3.4e38f;
    int   biA = 0, biB = 0, biC = 0, biD = 0;
    for (int jb = 0; jb < NN; jb += 32) {
        int j = jb + lane;
        float4 p = xb[j];
        float dA = fmaf(txA, p.x, fmaf(tyA, p.y, fmaf(tzA, p.z, -p.w)));
        float dB = fmaf(txB, p.x, fmaf(tyB, p.y, fmaf(tzB, p.z, -p.w)));
        float dC = fmaf(txC, p.x, fmaf(tyC, p.y, fmaf(tzC, p.z, -p.w)));
        float dD = fmaf(txD, p.x, fmaf(tyD, p.y, fmaf(tzD, p.z, -p.w)));
        bool pA = (dA >= tsA), pB = (dB >= tsB), pC = (dC >= tsC), pD = (dD >= tsD);
        unsigned m;
        while ((m = __ballot_sync(F, pA)) != 0) {
            int src = __ffs(m) - 1;
            float dc = __shfl_sync(F, dA, src);
            int   jc = __shfl_sync(F, j, src);
            if (lane == src) pA = false;
            int pc = __popc(__ballot_sync(F, bvA >= dc));
            float upv = __shfl_up_sync(F, bvA, 1);
            int   upi = __shfl_up_sync(F, biA, 1);
            if (lane >= pc) {
                if (lane == pc) { bvA = dc; biA = jc; }
                else            { bvA = upv; biA = upi; }
            }
        }
        while ((m = __ballot_sync(F, pB)) != 0) {
            int src = __ffs(m) - 1;
            float dc = __shfl_sync(F, dB, src);
            int   jc = __shfl_sync(F, j, src);
            if (lane == src) pB = false;
            int pc = __popc(__ballot_sync(F, bvB >= dc));
            float upv = __shfl_up_sync(F, bvB, 1);
            int   upi = __shfl_up_sync(F, biB, 1);
            if (lane >= pc) {
                if (lane == pc) { bvB = dc; biB = jc; }
                else            { bvB = upv; biB = upi; }
            }
        }
        while ((m = __ballot_sync(F, pC)) != 0) {
            int src = __ffs(m) - 1;
            float dc = __shfl_sync(F, dC, src);
            int   jc = __shfl_sync(F, j, src);
            if (lane == src) pC = false;
            int pc = __popc(__ballot_sync(F, bvC >= dc));
            float upv = __shfl_up_sync(F, bvC, 1);
            int   upi = __shfl_up_sync(F, biC, 1);
            if (lane >= pc) {
                if (lane == pc) { bvC = dc; biC = jc; }
                else            { bvC = upv; biC = upi; }
            }
        }
        while ((m = __ballot_sync(F, pD)) != 0) {
            int src = __ffs(m) - 1;
            float dc = __shfl_sync(F, dD, src);
            int   jc = __shfl_sync(F, j, src);
            if (lane == src) pD = false;
            int pc = __popc(__ballot_sync(F, bvD >= dc));
            float upv = __shfl_up_sync(F, bvD, 1);
            int   upi = __shfl_up_sync(F, biD, 1);
            if (lane >= pc) {
                if (lane == pc) { bvD = dc; biD = jc; }
                else            { bvD = upv; biD = upi; }
            }
        }
    }
    d_idx[((b * NN + i0) << 5) + lane]     = biA;
    d_idx[((b * NN + i0 + 1) << 5) + lane] = biB;
    d_idx[((b * NN + i0 + 2) << 5) + lane] = biC;
    d_idx[((b * NN + i0 + 3) << 5) + lane] = biD;
}

// ---------------- fused edge-MLP: all activations in fragments ---------------
// CTA = 8 points x 32 nbrs = 256 edges. 8 warps x 32 rows. 2 CTAs/SM.
__global__ void __launch_bounds__(256, 2) edge_mlp_kernel(
    const float* __restrict__ w1, const float* __restrict__ b1,
    const float* __restrict__ b2, const float* __restrict__ b3) {
    extern __shared__ char sm[];
    const uint32_t S = smem_u32(sm);
    int tid = threadIdx.x, w = tid >> 5, l = tid & 31;
    int b = blockIdx.x >> 9;
    int pbase = (blockIdx.x & 511) << 3;

    // ---- W3 chunks 0,1 in flight immediately ----
    {
        const char* src = (const char*)d_w3h;
        #pragma unroll
        for (int r = 0; r < 8; ++r) {
            int idx = tid + r * 256;
            int n = idx >> 4, q = idx & 15;
            cpasync16(S + SM_WB0 + n * 272 + q * 16, src + n * 256 + q * 16);
        }
        cpcommit();
        src += 128 * 256;
        #pragma unroll
        for (int r = 0; r < 8; ++r) {
            int idx = tid + r * 256;
            int n = idx >> 4, q = idx & 15;
            cpasync16(S + SM_WB1 + n * 272 + q * 16, src + n * 256 + q * 16);
        }
        cpcommit();
    }
    // ---- consts, W2, edge gather ----
    float* C = (float*)(sm + SM_CONST);
    if (tid < 192) C[tid] = w1[tid];
    else if (tid - 192 < 64) C[tid] = b1[tid - 192];
    if (tid < 128) C[256 + tid] = b2[tid];
    #pragma unroll
    for (int r = 0; r < 4; ++r) {
        int idx = tid + r * 256;
        int n = idx >> 3, q = idx & 7;
        *(uint4*)(sm + SM_WB2 + n * 144 + q * 16) = ((const uint4*)d_w2h)[idx];
    }
    {
        int p = tid >> 5, k = tid & 31;
        int i = pbase + p;
        int j = d_idx[((b * NN + i) << 5) + k];
        float4 xi = d_x4[b * NN + i];
        float4 xj = d_x4[b * NN + j];
        ((float4*)(sm + SM_X0))[tid] =
            make_float4(xj.x - xi.x, xj.y - xi.y, xj.z - xi.z, 0.f);
    }
    __syncthreads();

    // ---- L1 directly into A-fragment registers ----
    float4 ev[4];
    #pragma unroll
    for (int m = 0; m < 4; ++m)
        ev[m] = ((const float4*)(sm + SM_X0))[w * 32 + (l >> 2) + m * 8];
    uint32_t a2[2][4][4];
    #pragma unroll
    for (int mt = 0; mt < 2; ++mt)
        #pragma unroll
        for (int ks = 0; ks < 4; ++ks) {
            int o = ks * 16 + 2 * (l & 3);
            a2[mt][ks][0] = h1pair(C, ev[2 * mt],     o);
            a2[mt][ks][1] = h1pair(C, ev[2 * mt + 1], o);
            a2[mt][ks][2] = h1pair(C, ev[2 * mt],     o + 8);
            a2[mt][ks][3] = h1pair(C, ev[2 * mt + 1], o + 8);
        }

    // ---- L2: C-fragments become A3-fragments (no smem round trip) ----
    const uint32_t lB = (uint32_t)(l & 7) * 144 + (uint32_t)(l >> 3) * 16;
    uint32_t a3[2][8][4];
    {
        const __half2 z2 = __float2half2_rn(0.f);
        #pragma unroll
        for (int nt = 0; nt < 16; ++nt) {
            uint32_t c[2][2] = {{0u, 0u}, {0u, 0u}};
            #pragma unroll
            for (int kp = 0; kp < 2; ++kp) {
                uint32_t b4[4];
                ldsm4(b4[0], b4[1], b4[2], b4[3],
                      S + SM_WB2 + (uint32_t)(nt * 8) * 144 + lB + kp * 64);
                #pragma unroll
                for (int mt = 0; mt < 2; ++mt) {
                    mma16816h(c[mt], a2[mt][2 * kp],     b4[0], b4[1]);
                    mma16816h(c[mt], a2[mt][2 * kp + 1], b4[2], b4[3]);
                }
            }
            int colb = nt * 8 + 2 * (l & 3);
            __half2 bia = __floats2half2_rn(C[256 + colb], C[256 + colb + 1]);
            #pragma unroll
            for (int mt = 0; mt < 2; ++mt) {
                __half2 v0 = __hmax2(__hadd2(*(__half2*)&c[mt][0], bia), z2);
                __half2 v1 = __hmax2(__hadd2(*(__half2*)&c[mt][1], bia), z2);
                a3[mt][nt >> 1][(nt & 1) * 2 + 0] = *(uint32_t*)&v0;
                a3[mt][nt >> 1][(nt & 1) * 2 + 1] = *(uint32_t*)&v1;
            }
        }
    }

    // ---- L3: 8 chunks x 128 cols; deferred-by-2 epilogue reductions ----
    const uint32_t lB2 = (uint32_t)(l & 7) * 272 + (uint32_t)(l >> 3) * 16;
    uint32_t* cmaxu = (uint32_t*)(sm + SM_CMAX);
    for (int ch = 0; ch < 8; ++ch) {
        cpwait1();
        __syncthreads();
        const uint32_t Wb = S + ((ch & 1) ? SM_WB1 : SM_WB0);
        for (int qq = 0; qq < 8; qq += 2) {
            uint32_t mxr[2][2];     // [sub][n] register partial maxes
            #pragma unroll
            for (int s = 0; s < 2; ++s) {
                int pair = (qq + s + w) & 7;
                int nt0 = pair * 2;
                uint32_t bb[2][4][4];
                #pragma unroll
                for (int n = 0; n < 2; ++n)
                    #pragma unroll
                    for (int kp = 0; kp < 4; ++kp)
                        ldsm4(bb[n][kp][0], bb[n][kp][1], bb[n][kp][2], bb[n][kp][3],
                              Wb + (uint32_t)((nt0 + n) * 8) * 272 + lB2 + kp * 64);
                uint32_t c[2][2][2] = {};
                #pragma unroll
                for (int kp = 0; kp < 4; ++kp)
                    #pragma unroll
                    for (int n = 0; n < 2; ++n)
                        #pragma unroll
                        for (int mt = 0; mt < 2; ++mt) {
                            mma16816h(c[n][mt], a3[mt][2 * kp],     bb[n][kp][0], bb[n][kp][1]);
                            mma16816h(c[n][mt], a3[mt][2 * kp + 1], bb[n][kp][2], bb[n][kp][3]);
                        }
                #pragma unroll
                for (int n = 0; n < 2; ++n) {
                    __half2 mx = __hmax2(
                        __hmax2(*(__half2*)&c[n][0][0], *(__half2*)&c[n][0][1]),
                        __hmax2(*(__half2*)&c[n][1][0], *(__half2*)&c[n][1][1]));
                    mxr[s][n] = *(uint32_t*)&mx;
                }
            }
            // 4 independent shfl-reduce chains (ILP hides latency)
            #pragma unroll
            for (int s = 0; s < 2; ++s)
                #pragma unroll
                for (int n = 0; n < 2; ++n) {
                    __half2 mx = *(__half2*)&mxr[s][n];
                    #pragma unroll
                    for (int off = 4; off < 32; off <<= 1) {
                        uint32_t o = __shfl_xor_sync(0xffffffffu, *(uint32_t*)&mx, off);
                        mx = __hmax2(mx, *(__half2*)&o);
                    }
                    if (l < 4) {
                        int pair = (qq + s + w) & 7;
                        cmaxu[w * 512 + ch * 64 + (pair * 2 + n) * 4 + l] = *(uint32_t*)&mx;
                    }
                }
        }
        __syncthreads();
        if (ch + 2 < 8) {
            const char* src = (const char*)(d_w3h + (ch + 2) * 128 * 128);
            #pragma unroll
            for (int r = 0; r < 8; ++r) {
                int idx = tid + r * 256;
                int n = idx >> 4, qq2 = idx & 15;
                cpasync16(Wb + n * 272 + qq2 * 16, src + n * 256 + qq2 * 16);
            }
        }
        cpcommit();
    }

    // ---- cross-warp reduce + bias + relu + atomics ----
    #pragma unroll
    for (int r = 0; r < 2; ++r) {
        int ci = tid + r * 256;                // half2 index: cols 2ci, 2ci+1
        uint32_t mu = cmaxu[ci];
        __half2 m = *(__half2*)&mu;
        #pragma unroll
        for (int ww = 1; ww < 8; ++ww) {
            uint32_t o = cmaxu[ww * 512 + ci];
            m = __hmax2(m, *(__half2*)&o);
        }
        float2 f = __half22float2(m);
        int col = 2 * ci;
        float v0 = fmaxf(f.x + __ldg(&b3[col]),     0.f);
        float v1 = fmaxf(f.y + __ldg(&b3[col + 1]), 0.f);
        atomicMax((int*)&d_g[b * 1024 + col],     __float_as_int(v0));
        atomicMax((int*)&d_g[b * 1024 + col + 1], __float_as_int(v1));
    }
}

// ---------------- FC head ---------------------------------------------------
__global__ void __launch_bounds__(256) head1_kernel(
    const float* __restrict__ fw1, const float* __restrict__ fb1) {
    __shared__ float gs[1024];
    int b = blockIdx.x >> 3, part = blockIdx.x & 7;
    int tid = threadIdx.x, w = tid >> 5, l = tid & 31;
    for (int v = tid; v < 1024; v += 256) gs[v] = d_g[b * 1024 + v];
    __syncthreads();
    const float4* gr = (const float4*)gs;
    for (int s = 0; s < 8; ++s) {
        int o = part * 64 + w * 8 + s;
        const float4* wr = (const float4*)(fw1 + o * 1024);
        float acc = 0.f;
        #pragma unroll
        for (int q = 0; q < 8; ++q) {
            float4 a = wr[l + q * 32], g4 = gr[l + q * 32];
            acc += a.x * g4.x + a.y * g4.y + a.z * g4.z + a.w * g4.w;
        }
        #pragma unroll
        for (int off = 16; off; off >>= 1) acc += __shfl_xor_sync(0xffffffffu, acc, off);
        if (l == 0) d_f1[b * 512 + o] = fmaxf(acc + fb1[o], 0.f);
    }
}

__global__ void __launch_bounds__(256) head2_kernel(
    const float* __restrict__ fw2, const float* __restrict__ fb2,
    const float* __restrict__ fw3, const float* __restrict__ fb3) {
    __shared__ float f1s[512], f2s[256];
    int b = blockIdx.x, tid = threadIdx.x, w = tid >> 5, l = tid & 31;
    for (int v = tid; v < 512; v += 256) f1s[v] = d_f1[b * 512 + v];
    __syncthreads();
    const float4* f1r = (const float4*)f1s;
    for (int s = 0; s < 32; ++s) {
        int o = w * 32 + s;
        const float4* wr = (const float4*)(fw2 + o * 512);
        float acc = 0.f;
        #pragma unroll
        for (int q = 0; q < 4; ++q) {
            float4 a = wr[l + q * 32], g4 = f1r[l + q * 32];
            acc += a.x * g4.x + a.y * g4.y + a.z * g4.z + a.w * g4.w;
        }
        #pragma unroll
        for (int off = 16; off; off >>= 1) acc += __shfl_xor_sync(0xffffffffu, acc, off);
        if (l == 0) f2s[o] = fmaxf(acc + fb2[o], 0.f);
    }
    __syncthreads();
    const float4* f2r = (const float4*)f2s;
    for (int o = w; o < 9; o += 8) {
        const float4* wr = (const float4*)(fw3 + o * 256);
        float acc = 0.f;
        #pragma unroll
        for (int q = 0; q < 2; ++q) {
            float4 a = wr[l + q * 32], g4 = f2r[l + q * 32];
            acc += a.x * g4.x + a.y * g4.y + a.z * g4.z + a.w * g4.w;
        }
        #pragma unroll
        for (int off = 16; off; off >>= 1) acc += __shfl_xor_sync(0xffffffffu, acc, off);
        if (l == 0) {
            float s = acc + fb3[o];
            if (o == 0 || o == 4 || o == 8) s += 1.f;
            d_tm[b * 9 + o] = s;
        }
    }
}

// ---------------- out = bmm(x^T, t)^T --------------------------------------
__global__ void final_kernel(const float* __restrict__ x, float* __restrict__ out) {
    int id = blockIdx.x * blockDim.x + threadIdx.x;
    int b = id >> 12, n = id & (NN - 1);
    const float* xb = x + (size_t)b * 3 * NN;
    float a0 = xb[n], a1 = xb[NN + n], a2 = xb[2 * NN + n];
    const float* t = d_tm + b * 9;
    float* ob = out + (size_t)b * 3 * NN;
    ob[n]          = a0 * t[0] + a1 * t[3] + a2 * t[6];
    ob[NN + n]     = a0 * t[1] + a1 * t[4] + a2 * t[7];
    ob[2 * NN + n] = a0 * t[2] + a1 * t[5] + a2 * t[8];
}

extern "C" void kernel_launch(void* const* d_in, const int* in_sizes, int n_in,
                              void* d_out, int out_size) {
    const float* x   = (const float*)d_in[0];
    const float* w1  = (const float*)d_in[1];
    const float* b1  = (const float*)d_in[2];
    const float* w2  = (const float*)d_in[3];
    const float* b2  = (const float*)d_in[4];
    const float* w3  = (const float*)d_in[5];
    const float* b3  = (const float*)d_in[6];
    const float* fw1 = (const float*)d_in[7];
    const float* fb1 = (const float*)d_in[8];
    const float* fw2 = (const float*)d_in[9];
    const float* fb2 = (const float*)d_in[10];
    const float* fw3 = (const float*)d_in[11];
    const float* fb3 = (const float*)d_in[12];
    float* out = (float*)d_out;

    cudaFuncSetAttribute(edge_mlp_kernel,
                         cudaFuncAttributeMaxDynamicSharedMemorySize, SM_TOT);

    prep_x_kernel<<<BB * NN / 256, 256>>>(x);          // idx 0
    knn_kernel<<<BB * NN / 32, 256>>>();               // idx 1 (4 points/warp)
    prep_wg_kernel<<<512, 256>>>(w2, w3);              // idx 2
    edge_mlp_kernel<<<BB * NN / 8, 256, SM_TOT>>>(w1, b1, b2, b3);  // idx 3 (profiled)
    head1_kernel<<<BB * 8, 256>>>(fw1, fb1);           // idx 4
    head2_kernel<<<BB, 256>>>(fw2, fb2, fw3, fb3);     // idx 5
    final_kernel<<<BB * NN / 256, 256>>>(x, out);      // idx 6
}

// round 15
// speedup vs baseline: 1.0084x; 1.0084x over previous
#include <cuda_runtime.h>
#include <cuda_fp16.h>
#include <cstdint>

#define BB 16
#define NN 4096

// ---------------- persistent device scratch --------------------------------
__device__ float4 d_x4[BB * NN];
__device__ int    d_idx[BB * NN * 32];
__device__ __half d_w2h[128 * 64];      // [n=128][k=64]
__device__ __half d_w3h[1024 * 128];    // [n=1024][k=128]
__device__ float  d_g[BB * 1024];
__device__ float  d_f1[BB * 512];
__device__ float  d_tm[BB * 9];

// ---------------- smem map (bytes) -----------------------------------------
#define SM_WB0   0        /* W3 chunk buf0: 128 x 272 = 34816 */
#define SM_WB1   34816    /* W3 chunk buf1 */
#define SM_WB2   69632    /* W2: 128 x 144 = 18432 */
#define SM_CMAX  88064    /* 8 warps x 512 u32 (half2 col-max) = 16384 */
#define SM_X0    104448   /* 256 x float4 = 4096 */
#define SM_CONST 108544   /* w1(192f) b1(64f) b2(128f) = 1536, pad 2048 */
#define SM_TOT   110592

// ---------------- helpers ---------------------------------------------------
__device__ __forceinline__ uint32_t smem_u32(const void* p) {
    uint32_t a;
    asm("{ .reg .u64 t; cvta.to.shared.u64 t, %1; cvt.u32.u64 %0, t; }"
        : "=r"(a) : "l"(p));
    return a;
}
__device__ __forceinline__ void ldsm4(uint32_t& r0, uint32_t& r1,
                                      uint32_t& r2, uint32_t& r3, uint32_t a) {
    asm volatile("ldmatrix.sync.aligned.m8n8.x4.shared.b16 {%0,%1,%2,%3}, [%4];"
                 : "=r"(r0), "=r"(r1), "=r"(r2), "=r"(r3) : "r"(a));
}
__device__ __forceinline__ void mma16816h(uint32_t* c, const uint32_t* a,
                                          uint32_t b0, uint32_t b1) {
    asm volatile("mma.sync.aligned.m16n8k16.row.col.f16.f16.f16.f16 "
                 "{%0,%1}, {%2,%3,%4,%5}, {%6,%7}, {%0,%1};"
                 : "+r"(c[0]), "+r"(c[1])
                 : "r"(a[0]), "r"(a[1]), "r"(a[2]), "r"(a[3]), "r"(b0), "r"(b1));
}
__device__ __forceinline__ void cpasync16(uint32_t dst, const void* src) {
    asm volatile("cp.async.cg.shared.global [%0], [%1], 16;" :: "r"(dst), "l"(src));
}
__device__ __forceinline__ void cpcommit() { asm volatile("cp.async.commit_group;"); }
__device__ __forceinline__ void cpwait1()  { asm volatile("cp.async.wait_group 1;"); }

// relu(W1[o..o+1] . e + b1) packed as half2 — feeds A-fragments directly
__device__ __forceinline__ uint32_t h1pair(const float* C, float4 e, int o) {
    float v0 = fmaxf(fmaf(e.x, C[3 * o + 0], fmaf(e.y, C[3 * o + 1],
                     fmaf(e.z, C[3 * o + 2], C[192 + o]))), 0.f);
    float v1 = fmaxf(fmaf(e.x, C[3 * o + 3], fmaf(e.y, C[3 * o + 4],
                     fmaf(e.z, C[3 * o + 5], C[192 + o + 1]))), 0.f);
    __half2 h = __floats2half2_rn(v0, v1);
    return *(uint32_t*)&h;
}

// ---------------- prep (merged): x pack + w3/w2 fp16 + zero g ---------------
__global__ void prep_all_kernel(const float* __restrict__ x,
                                const float* __restrict__ w2,
                                const float* __restrict__ w3) {
    int id = blockIdx.x * blockDim.x + threadIdx.x;
    if (id < 1024 * 128) d_w3h[id] = __float2half(w3[id]);
    if (id < 128 * 64)   d_w2h[id] = __float2half(w2[id]);
    if (id < BB * 1024)  d_g[id] = 0.f;
    if (id < BB * NN) {
        int b = id >> 12, j = id & (NN - 1);
        const float* xb = x + (size_t)b * 3 * NN;
        float a0 = xb[j], a1 = xb[NN + j], a2 = xb[2 * NN + j];
        d_x4[id] = make_float4(a0, a1, a2, a0 * a0 + a1 * a1 + a2 * a2);
    }
}

// ---------------- kNN: warp handles 2 points, exact two-pass ----------------
// One candidate load serves both points; per-point threshold + insertion
// logic identical to the single-point version (sets bit-identical).
__global__ void __launch_bounds__(256) knn_kernel() {
    const unsigned F = 0xffffffffu;
    int warp = threadIdx.x >> 5, lane = threadIdx.x & 31;
    int b = blockIdx.x >> 8;                          // 256 blocks per batch
    int i0 = ((blockIdx.x & 255) << 4) + warp * 2;    // 16 points per block
    const float4* xb = d_x4 + b * NN;
    float4 xA = xb[i0], xB = xb[i0 + 1];
    float txA = 2.f * xA.x, tyA = 2.f * xA.y, tzA = 2.f * xA.z;
    float txB = 2.f * xB.x, tyB = 2.f * xB.y, tzB = 2.f * xB.z;

    // ---- pass 1: per-lane maxes for both points (shared loads) ----
    float lmA = -3.4e38f, lmB = -3.4e38f;
    #pragma unroll 4
    for (int jb = 0; jb < NN; jb += 32) {
        float4 p = xb[jb + lane];
        float dA = fmaf(txA, p.x, fmaf(tyA, p.y, fmaf(tzA, p.z, -p.w)));
        float dB = fmaf(txB, p.x, fmaf(tyB, p.y, fmaf(tzB, p.z, -p.w)));
        lmA = fmaxf(lmA, dA);
        lmB = fmaxf(lmB, dB);
    }
    float tsA = lmA, tsB = lmB;
    #pragma unroll
    for (int off = 16; off; off >>= 1) {
        tsA = fminf(tsA, __shfl_xor_sync(F, tsA, off));
        tsB = fminf(tsB, __shfl_xor_sync(F, tsB, off));
    }

    // ---- pass 2: collect candidates >= t* per point ----
    float bvA = -3.4e38f, bvB = -3.4e38f;
    int   biA = 0,        biB = 0;
    #pragma unroll 2
    for (int jb = 0; jb < NN; jb += 32) {
        int j = jb + lane;
        float4 p = xb[j];
        float dA = fmaf(txA, p.x, fmaf(tyA, p.y, fmaf(tzA, p.z, -p.w)));
        float dB = fmaf(txB, p.x, fmaf(tyB, p.y, fmaf(tzB, p.z, -p.w)));
        bool pA = (dA >= tsA), pB = (dB >= tsB);
        unsigned m;
        while ((m = __ballot_sync(F, pA)) != 0) {
            int src = __ffs(m) - 1;
            float dc = __shfl_sync(F, dA, src);
            int   jc = __shfl_sync(F, j, src);
            if (lane == src) pA = false;
            int pc = __popc(__ballot_sync(F, bvA >= dc));
            float upv = __shfl_up_sync(F, bvA, 1);
            int   upi = __shfl_up_sync(F, biA, 1);
            if (lane >= pc) {
                if (lane == pc) { bvA = dc; biA = jc; }
                else            { bvA = upv; biA = upi; }
            }
        }
        while ((m = __ballot_sync(F, pB)) != 0) {
            int src = __ffs(m) - 1;
            float dc = __shfl_sync(F, dB, src);
            int   jc = __shfl_sync(F, j, src);
            if (lane == src) pB = false;
            int pc = __popc(__ballot_sync(F, bvB >= dc));
            float upv = __shfl_up_sync(F, bvB, 1);
            int   upi = __shfl_up_sync(F, biB, 1);
            if (lane >= pc) {
                if (lane == pc) { bvB = dc; biB = jc; }
                else            { bvB = upv; biB = upi; }
            }
        }
    }
    d_idx[((b * NN + i0) << 5) + lane]       = biA;
    d_idx[((b * NN + i0 + 1) << 5) + lane]   = biB;
}

// ---------------- fused edge-MLP: all activations in fragments ---------------
// CTA = 8 points x 32 nbrs = 256 edges. 8 warps x 32 rows. 2 CTAs/SM.
__global__ void __launch_bounds__(256, 2) edge_mlp_kernel(
    const float* __restrict__ w1, const float* __restrict__ b1,
    const float* __restrict__ b2, const float* __restrict__ b3) {
    extern __shared__ char sm[];
    const uint32_t S = smem_u32(sm);
    int tid = threadIdx.x, w = tid >> 5, l = tid & 31;
    int b = blockIdx.x >> 9;
    int pbase = (blockIdx.x & 511) << 3;

    // ---- W3 chunks 0,1 in flight immediately ----
    {
        const char* src = (const char*)d_w3h;
        #pragma unroll
        for (int r = 0; r < 8; ++r) {
            int idx = tid + r * 256;
            int n = idx >> 4, q = idx & 15;
            cpasync16(S + SM_WB0 + n * 272 + q * 16, src + n * 256 + q * 16);
        }
        cpcommit();
        src += 128 * 256;
        #pragma unroll
        for (int r = 0; r < 8; ++r) {
            int idx = tid + r * 256;
            int n = idx >> 4, q = idx & 15;
            cpasync16(S + SM_WB1 + n * 272 + q * 16, src + n * 256 + q * 16);
        }
        cpcommit();
    }
    // ---- consts, W2, edge gather ----
    float* C = (float*)(sm + SM_CONST);
    if (tid < 192) C[tid] = w1[tid];
    else if (tid - 192 < 64) C[tid] = b1[tid - 192];
    if (tid < 128) C[256 + tid] = b2[tid];
    #pragma unroll
    for (int r = 0; r < 4; ++r) {
        int idx = tid + r * 256;
        int n = idx >> 3, q = idx & 7;
        *(uint4*)(sm + SM_WB2 + n * 144 + q * 16) = ((const uint4*)d_w2h)[idx];
    }
    {
        int p = tid >> 5, k = tid & 31;
        int i = pbase + p;
        int j = d_idx[((b * NN + i) << 5) + k];
        float4 xi = d_x4[b * NN + i];
        float4 xj = d_x4[b * NN + j];
        ((float4*)(sm + SM_X0))[tid] =
            make_float4(xj.x - xi.x, xj.y - xi.y, xj.z - xi.z, 0.f);
    }
    __syncthreads();

    // ---- L1 directly into A-fragment registers ----
    float4 ev[4];
    #pragma unroll
    for (int m = 0; m < 4; ++m)
        ev[m] = ((const float4*)(sm + SM_X0))[w * 32 + (l >> 2) + m * 8];
    uint32_t a2[2][4][4];
    #pragma unroll
    for (int mt = 0; mt < 2; ++mt)
        #pragma unroll
        for (int ks = 0; ks < 4; ++ks) {
            int o = ks * 16 + 2 * (l & 3);
            a2[mt][ks][0] = h1pair(C, ev[2 * mt],     o);
            a2[mt][ks][1] = h1pair(C, ev[2 * mt + 1], o);
            a2[mt][ks][2] = h1pair(C, ev[2 * mt],     o + 8);
            a2[mt][ks][3] = h1pair(C, ev[2 * mt + 1], o + 8);
        }

    // ---- L2: C-fragments become A3-fragments (no smem round trip) ----
    const uint32_t lB = (uint32_t)(l & 7) * 144 + (uint32_t)(l >> 3) * 16;
    uint32_t a3[2][8][4];
    {
        const __half2 z2 = __float2half2_rn(0.f);
        #pragma unroll
        for (int nt = 0; nt < 16; ++nt) {
            uint32_t c[2][2] = {{0u, 0u}, {0u, 0u}};
            #pragma unroll
            for (int kp = 0; kp < 2; ++kp) {
                uint32_t b4[4];
                ldsm4(b4[0], b4[1], b4[2], b4[3],
                      S + SM_WB2 + (uint32_t)(nt * 8) * 144 + lB + kp * 64);
                #pragma unroll
                for (int mt = 0; mt < 2; ++mt) {
                    mma16816h(c[mt], a2[mt][2 * kp],     b4[0], b4[1]);
                    mma16816h(c[mt], a2[mt][2 * kp + 1], b4[2], b4[3]);
                }
            }
            int colb = nt * 8 + 2 * (l & 3);
            __half2 bia = __floats2half2_rn(C[256 + colb], C[256 + colb + 1]);
            #pragma unroll
            for (int mt = 0; mt < 2; ++mt) {
                __half2 v0 = __hmax2(__hadd2(*(__half2*)&c[mt][0], bia), z2);
                __half2 v1 = __hmax2(__hadd2(*(__half2*)&c[mt][1], bia), z2);
                a3[mt][nt >> 1][(nt & 1) * 2 + 0] = *(uint32_t*)&v0;
                a3[mt][nt >> 1][(nt & 1) * 2 + 1] = *(uint32_t*)&v1;
            }
        }
    }

    // ---- L3: 8 chunks x 128 cols; deferred-by-2 epilogue reductions ----
    const uint32_t lB2 = (uint32_t)(l & 7) * 272 + (uint32_t)(l >> 3) * 16;
    uint32_t* cmaxu = (uint32_t*)(sm + SM_CMAX);
    for (int ch = 0; ch < 8; ++ch) {
        cpwait1();
        __syncthreads();
        const uint32_t Wb = S + ((ch & 1) ? SM_WB1 : SM_WB0);
        for (int qq = 0; qq < 8; qq += 2) {
            uint32_t mxr[2][2];     // [sub][n] register partial maxes
            #pragma unroll
            for (int s = 0; s < 2; ++s) {
                int pair = (qq + s + w) & 7;
                int nt0 = pair * 2;
                uint32_t bb[2][4][4];
                #pragma unroll
                for (int n = 0; n < 2; ++n)
                    #pragma unroll
                    for (int kp = 0; kp < 4; ++kp)
                        ldsm4(bb[n][kp][0], bb[n][kp][1], bb[n][kp][2], bb[n][kp][3],
                              Wb + (uint32_t)((nt0 + n) * 8) * 272 + lB2 + kp * 64);
                uint32_t c[2][2][2] = {};
                #pragma unroll
                for (int kp = 0; kp < 4; ++kp)
                    #pragma unroll
                    for (int n = 0; n < 2; ++n)
                        #pragma unroll
                        for (int mt = 0; mt < 2; ++mt) {
                            mma16816h(c[n][mt], a3[mt][2 * kp],     bb[n][kp][0], bb[n][kp][1]);
                            mma16816h(c[n][mt], a3[mt][2 * kp + 1], bb[n][kp][2], bb[n][kp][3]);
                        }
                #pragma unroll
                for (int n = 0; n < 2; ++n) {
                    __half2 mx = __hmax2(
                        __hmax2(*(__half2*)&c[n][0][0], *(__half2*)&c[n][0][1]),
                        __hmax2(*(__half2*)&c[n][1][0], *(__half2*)&c[n][1][1]));
                    mxr[s][n] = *(uint32_t*)&mx;
                }
            }
            // 4 independent shfl-reduce chains (ILP hides latency)
            #pragma unroll
            for (int s = 0; s < 2; ++s)
                #pragma unroll
                for (int n = 0; n < 2; ++n) {
                    __half2 mx = *(__half2*)&mxr[s][n];
                    #pragma unroll
                    for (int off = 4; off < 32; off <<= 1) {
                        uint32_t o = __shfl_xor_sync(0xffffffffu, *(uint32_t*)&mx, off);
                        mx = __hmax2(mx, *(__half2*)&o);
                    }
                    if (l < 4) {
                        int pair = (qq + s + w) & 7;
                        cmaxu[w * 512 + ch * 64 + (pair * 2 + n) * 4 + l] = *(uint32_t*)&mx;
                    }
                }
        }
        __syncthreads();
        if (ch + 2 < 8) {
            const char* src = (const char*)(d_w3h + (ch + 2) * 128 * 128);
            #pragma unroll
            for (int r = 0; r < 8; ++r) {
                int idx = tid + r * 256;
                int n = idx >> 4, qq2 = idx & 15;
                cpasync16(Wb + n * 272 + qq2 * 16, src + n * 256 + qq2 * 16);
            }
        }
        cpcommit();
    }

    // ---- cross-warp reduce + bias + relu + atomics ----
    #pragma unroll
    for (int r = 0; r < 2; ++r) {
        int ci = tid + r * 256;                // half2 index: cols 2ci, 2ci+1
        uint32_t mu = cmaxu[ci];
        __half2 m = *(__half2*)&mu;
        #pragma unroll
        for (int ww = 1; ww < 8; ++ww) {
            uint32_t o = cmaxu[ww * 512 + ci];
            m = __hmax2(m, *(__half2*)&o);
        }
        float2 f = __half22float2(m);
        int col = 2 * ci;
        float v0 = fmaxf(f.x + __ldg(&b3[col]),     0.f);
        float v1 = fmaxf(f.y + __ldg(&b3[col + 1]), 0.f);
        atomicMax((int*)&d_g[b * 1024 + col],     __float_as_int(v0));
        atomicMax((int*)&d_g[b * 1024 + col + 1], __float_as_int(v1));
    }
}

// ---------------- FC head ---------------------------------------------------
__global__ void __launch_bounds__(256) head1_kernel(
    const float* __restrict__ fw1, const float* __restrict__ fb1) {
    __shared__ float gs[1024];
    int b = blockIdx.x >> 3, part = blockIdx.x & 7;
    int tid = threadIdx.x, w = tid >> 5, l = tid & 31;
    for (int v = tid; v < 1024; v += 256) gs[v] = d_g[b * 1024 + v];
    __syncthreads();
    const float4* gr = (const float4*)gs;
    for (int s = 0; s < 8; ++s) {
        int o = part * 64 + w * 8 + s;
        const float4* wr = (const float4*)(fw1 + o * 1024);
        float acc = 0.f;
        #pragma unroll
        for (int q = 0; q < 8; ++q) {
            float4 a = wr[l + q * 32], g4 = gr[l + q * 32];
            acc += a.x * g4.x + a.y * g4.y + a.z * g4.z + a.w * g4.w;
        }
        #pragma unroll
        for (int off = 16; off; off >>= 1) acc += __shfl_xor_sync(0xffffffffu, acc, off);
        if (l == 0) d_f1[b * 512 + o] = fmaxf(acc + fb1[o], 0.f);
    }
}

__global__ void __launch_bounds__(256) head2_kernel(
    const float* __restrict__ fw2, const float* __restrict__ fb2,
    const float* __restrict__ fw3, const float* __restrict__ fb3) {
    __shared__ float f1s[512], f2s[256];
    int b = blockIdx.x, tid = threadIdx.x, w = tid >> 5, l = tid & 31;
    for (int v = tid; v < 512; v += 256) f1s[v] = d_f1[b * 512 + v];
    __syncthreads();
    const float4* f1r = (const float4*)f1s;
    for (int s = 0; s < 32; ++s) {
        int o = w * 32 + s;
        const float4* wr = (const float4*)(fw2 + o * 512);
        float acc = 0.f;
        #pragma unroll
        for (int q = 0; q < 4; ++q) {
            float4 a = wr[l + q * 32], g4 = f1r[l + q * 32];
            acc += a.x * g4.x + a.y * g4.y + a.z * g4.z + a.w * g4.w;
        }
        #pragma unroll
        for (int off = 16; off; off >>= 1) acc += __shfl_xor_sync(0xffffffffu, acc, off);
        if (l == 0) f2s[o] = fmaxf(acc + fb2[o], 0.f);
    }
    __syncthreads();
    const float4* f2r = (const float4*)f2s;
    for (int o = w; o < 9; o += 8) {
        const float4* wr = (const float4*)(fw3 + o * 256);
        float acc = 0.f;
        #pragma unroll
        for (int q = 0; q < 2; ++q) {
            float4 a = wr[l + q * 32], g4 = f2r[l + q * 32];
            acc += a.x * g4.x + a.y * g4.y + a.z * g4.z + a.w * g4.w;
        }
        #pragma unroll
        for (int off = 16; off; off >>= 1) acc += __shfl_xor_sync(0xffffffffu, acc, off);
        if (l == 0) {
            float s = acc + fb3[o];
            if (o == 0 || o == 4 || o == 8) s += 1.f;
            d_tm[b * 9 + o] = s;
        }
    }
}

// ---------------- out = bmm(x^T, t)^T --------------------------------------
__global__ void final_kernel(const float* __restrict__ x, float* __restrict__ out) {
    int id = blockIdx.x * blockDim.x + threadIdx.x;
    int b = id >> 12, n = id & (NN - 1);
    const float* xb = x + (size_t)b * 3 * NN;
    float a0 = xb[n], a1 = xb[NN + n], a2 = xb[2 * NN + n];
    const float* t = d_tm + b * 9;
    float* ob = out + (size_t)b * 3 * NN;
    ob[n]          = a0 * t[0] + a1 * t[3] + a2 * t[6];
    ob[NN + n]     = a0 * t[1] + a1 * t[4] + a2 * t[7];
    ob[2 * NN + n] = a0 * t[2] + a1 * t[5] + a2 * t[8];
}

extern "C" void kernel_launch(void* const* d_in, const int* in_sizes, int n_in,
                              void* d_out, int out_size) {
    const float* x   = (const float*)d_in[0];
    const float* w1  = (const float*)d_in[1];
    const float* b1  = (const float*)d_in[2];
    const float* w2  = (const float*)d_in[3];
    const float* b2  = (const float*)d_in[4];
    const float* w3  = (const float*)d_in[5];
    const float* b3  = (const float*)d_in[6];
    const float* fw1 = (const float*)d_in[7];
    const float* fb1 = (const float*)d_in[8];
    const float* fw2 = (const float*)d_in[9];
    const float* fb2 = (const float*)d_in[10];
    const float* fw3 = (const float*)d_in[11];
    const float* fb3 = (const float*)d_in[12];
    float* out = (float*)d_out;

    cudaFuncSetAttribute(edge_mlp_kernel,
                         cudaFuncAttributeMaxDynamicSharedMemorySize, SM_TOT);

    prep_all_kernel<<<512, 256>>>(x, w2, w3);          // idx 0 (merged prep)
    knn_kernel<<<BB * NN / 16, 256>>>();               // idx 1 (2 points/warp)
    edge_mlp_kernel<<<BB * NN / 8, 256, SM_TOT>>>(w1, b1, b2, b3);  // idx 2
    head1_kernel<<<BB * 8, 256>>>(fw1, fb1);           // idx 3
    head2_kernel<<<BB, 256>>>(fw2, fb2, fw3, fb3);     // idx 4
    final_kernel<<<BB * NN / 256, 256>>>(x, out);      // idx 5
}

// round 16
// speedup vs baseline: 1.0090x; 1.0006x over previous
#include <cuda_runtime.h>
#include <cuda_fp16.h>
#include <cstdint>

#define BB 16
#define NN 4096

// ---------------- persistent device scratch --------------------------------
__device__ float4 d_x4[BB * NN];
__device__ int    d_idx[BB * NN * 32];
__device__ __half d_w2h[128 * 64];      // [n=128][k=64]
__device__ __half d_w3h[1024 * 128];    // [n=1024][k=128]
__device__ float  d_g[BB * 1024];
__device__ float  d_f1[BB * 512];
__device__ float  d_tm[BB * 9];

// ---------------- smem map (bytes) -----------------------------------------
#define SM_WB0   0        /* W3 chunk buf0: 128 x 272 = 34816 */
#define SM_WB1   34816    /* W3 chunk buf1 */
#define SM_WB2   69632    /* W2: 128 x 144 = 18432 */
#define SM_CMAX  88064    /* 8 warps x 512 u32 (half2 col-max) = 16384 */
#define SM_X0    104448   /* 256 x float4 = 4096 */
#define SM_CONST 108544   /* w1(192f) b1(64f) b2(128f) = 1536, pad 2048 */
#define SM_TOT   110592

// ---------------- helpers ---------------------------------------------------
__device__ __forceinline__ uint32_t smem_u32(const void* p) {
    uint32_t a;
    asm("{ .reg .u64 t; cvta.to.shared.u64 t, %1; cvt.u32.u64 %0, t; }"
        : "=r"(a) : "l"(p));
    return a;
}
__device__ __forceinline__ void ldsm4(uint32_t& r0, uint32_t& r1,
                                      uint32_t& r2, uint32_t& r3, uint32_t a) {
    asm volatile("ldmatrix.sync.aligned.m8n8.x4.shared.b16 {%0,%1,%2,%3}, [%4];"
                 : "=r"(r0), "=r"(r1), "=r"(r2), "=r"(r3) : "r"(a));
}
__device__ __forceinline__ void mma16816h(uint32_t* c, const uint32_t* a,
                                          uint32_t b0, uint32_t b1) {
    asm volatile("mma.sync.aligned.m16n8k16.row.col.f16.f16.f16.f16 "
                 "{%0,%1}, {%2,%3,%4,%5}, {%6,%7}, {%0,%1};"
                 : "+r"(c[0]), "+r"(c[1])
                 : "r"(a[0]), "r"(a[1]), "r"(a[2]), "r"(a[3]), "r"(b0), "r"(b1));
}
__device__ __forceinline__ void cpasync16(uint32_t dst, const void* src) {
    asm volatile("cp.async.cg.shared.global [%0], [%1], 16;" :: "r"(dst), "l"(src));
}
__device__ __forceinline__ void cpcommit() { asm volatile("cp.async.commit_group;"); }
__device__ __forceinline__ void cpwait1()  { asm volatile("cp.async.wait_group 1;"); }

// relu(W1[o..o+1] . e + b1) packed as half2 — feeds A-fragments directly
__device__ __forceinline__ uint32_t h1pair(const float* C, float4 e, int o) {
    float v0 = fmaxf(fmaf(e.x, C[3 * o + 0], fmaf(e.y, C[3 * o + 1],
                     fmaf(e.z, C[3 * o + 2], C[192 + o]))), 0.f);
    float v1 = fmaxf(fmaf(e.x, C[3 * o + 3], fmaf(e.y, C[3 * o + 4],
                     fmaf(e.z, C[3 * o + 5], C[192 + o + 1]))), 0.f);
    __half2 h = __floats2half2_rn(v0, v1);
    return *(uint32_t*)&h;
}

// ---------------- prep (merged): x pack + w3/w2 fp16 + zero g ---------------
__global__ void prep_all_kernel(const float* __restrict__ x,
                                const float* __restrict__ w2,
                                const float* __restrict__ w3) {
    int id = blockIdx.x * blockDim.x + threadIdx.x;
    if (id < 1024 * 128) d_w3h[id] = __float2half(w3[id]);
    if (id < 128 * 64)   d_w2h[id] = __float2half(w2[id]);
    if (id < BB * 1024)  d_g[id] = 0.f;
    if (id < BB * NN) {
        int b = id >> 12, j = id & (NN - 1);
        const float* xb = x + (size_t)b * 3 * NN;
        float a0 = xb[j], a1 = xb[NN + j], a2 = xb[2 * NN + j];
        d_x4[id] = make_float4(a0, a1, a2, a0 * a0 + a1 * a1 + a2 * a2);
    }
}

// ---------------- kNN: warp handles 2 points, exact two-pass ----------------
__global__ void __launch_bounds__(256) knn_kernel() {
    const unsigned F = 0xffffffffu;
    int warp = threadIdx.x >> 5, lane = threadIdx.x & 31;
    int b = blockIdx.x >> 8;                          // 256 blocks per batch
    int i0 = ((blockIdx.x & 255) << 4) + warp * 2;    // 16 points per block
    const float4* xb = d_x4 + b * NN;
    float4 xA = xb[i0], xB = xb[i0 + 1];
    float txA = 2.f * xA.x, tyA = 2.f * xA.y, tzA = 2.f * xA.z;
    float txB = 2.f * xB.x, tyB = 2.f * xB.y, tzB = 2.f * xB.z;

    // ---- pass 1: per-lane maxes for both points (shared loads) ----
    float lmA = -3.4e38f, lmB = -3.4e38f;
    #pragma unroll 4
    for (int jb = 0; jb < NN; jb += 32) {
        float4 p = xb[jb + lane];
        float dA = fmaf(txA, p.x, fmaf(tyA, p.y, fmaf(tzA, p.z, -p.w)));
        float dB = fmaf(txB, p.x, fmaf(tyB, p.y, fmaf(tzB, p.z, -p.w)));
        lmA = fmaxf(lmA, dA);
        lmB = fmaxf(lmB, dB);
    }
    float tsA = lmA, tsB = lmB;
    #pragma unroll
    for (int off = 16; off; off >>= 1) {
        tsA = fminf(tsA, __shfl_xor_sync(F, tsA, off));
        tsB = fminf(tsB, __shfl_xor_sync(F, tsB, off));
    }

    // ---- pass 2: collect candidates >= t* per point ----
    float bvA = -3.4e38f, bvB = -3.4e38f;
    int   biA = 0,        biB = 0;
    #pragma unroll 2
    for (int jb = 0; jb < NN; jb += 32) {
        int j = jb + lane;
        float4 p = xb[j];
        float dA = fmaf(txA, p.x, fmaf(tyA, p.y, fmaf(tzA, p.z, -p.w)));
        float dB = fmaf(txB, p.x, fmaf(tyB, p.y, fmaf(tzB, p.z, -p.w)));
        bool pA = (dA >= tsA), pB = (dB >= tsB);
        unsigned m;
        while ((m = __ballot_sync(F, pA)) != 0) {
            int src = __ffs(m) - 1;
            float dc = __shfl_sync(F, dA, src);
            int   jc = __shfl_sync(F, j, src);
            if (lane == src) pA = false;
            int pc = __popc(__ballot_sync(F, bvA >= dc));
            float upv = __shfl_up_sync(F, bvA, 1);
            int   upi = __shfl_up_sync(F, biA, 1);
            if (lane >= pc) {
                if (lane == pc) { bvA = dc; biA = jc; }
                else            { bvA = upv; biA = upi; }
            }
        }
        while ((m = __ballot_sync(F, pB)) != 0) {
            int src = __ffs(m) - 1;
            float dc = __shfl_sync(F, dB, src);
            int   jc = __shfl_sync(F, j, src);
            if (lane == src) pB = false;
            int pc = __popc(__ballot_sync(F, bvB >= dc));
            float upv = __shfl_up_sync(F, bvB, 1);
            int   upi = __shfl_up_sync(F, biB, 1);
            if (lane >= pc) {
                if (lane == pc) { bvB = dc; biB = jc; }
                else            { bvB = upv; biB = upi; }
            }
        }
    }
    d_idx[((b * NN + i0) << 5) + lane]       = biA;
    d_idx[((b * NN + i0 + 1) << 5) + lane]   = biB;
}

// ---------------- fused edge-MLP: all activations in fragments ---------------
// CTA = 8 points x 32 nbrs = 256 edges. 8 warps x 32 rows. 2 CTAs/SM.
__global__ void __launch_bounds__(256, 2) edge_mlp_kernel(
    const float* __restrict__ w1, const float* __restrict__ b1,
    const float* __restrict__ b2, const float* __restrict__ b3) {
    extern __shared__ char sm[];
    const uint32_t S = smem_u32(sm);
    int tid = threadIdx.x, w = tid >> 5, l = tid & 31;
    int b = blockIdx.x >> 9;
    int pbase = (blockIdx.x & 511) << 3;

    // ---- W3 chunks 0,1 in flight immediately ----
    {
        const char* src = (const char*)d_w3h;
        #pragma unroll
        for (int r = 0; r < 8; ++r) {
            int idx = tid + r * 256;
            int n = idx >> 4, q = idx & 15;
            cpasync16(S + SM_WB0 + n * 272 + q * 16, src + n * 256 + q * 16);
        }
        cpcommit();
        src += 128 * 256;
        #pragma unroll
        for (int r = 0; r < 8; ++r) {
            int idx = tid + r * 256;
            int n = idx >> 4, q = idx & 15;
            cpasync16(S + SM_WB1 + n * 272 + q * 16, src + n * 256 + q * 16);
        }
        cpcommit();
    }
    // ---- consts, W2, edge gather ----
    float* C = (float*)(sm + SM_CONST);
    if (tid < 192) C[tid] = w1[tid];
    else if (tid - 192 < 64) C[tid] = b1[tid - 192];
    if (tid < 128) C[256 + tid] = b2[tid];
    #pragma unroll
    for (int r = 0; r < 4; ++r) {
        int idx = tid + r * 256;
        int n = idx >> 3, q = idx & 7;
        *(uint4*)(sm + SM_WB2 + n * 144 + q * 16) = ((const uint4*)d_w2h)[idx];
    }
    {
        int p = tid >> 5, k = tid & 31;
        int i = pbase + p;
        int j = d_idx[((b * NN + i) << 5) + k];
        float4 xi = d_x4[b * NN + i];
        float4 xj = d_x4[b * NN + j];
        ((float4*)(sm + SM_X0))[tid] =
            make_float4(xj.x - xi.x, xj.y - xi.y, xj.z - xi.z, 0.f);
    }
    __syncthreads();

    // ---- L1 directly into A-fragment registers ----
    float4 ev[4];
    #pragma unroll
    for (int m = 0; m < 4; ++m)
        ev[m] = ((const float4*)(sm + SM_X0))[w * 32 + (l >> 2) + m * 8];
    uint32_t a2[2][4][4];
    #pragma unroll
    for (int mt = 0; mt < 2; ++mt)
        #pragma unroll
        for (int ks = 0; ks < 4; ++ks) {
            int o = ks * 16 + 2 * (l & 3);
            a2[mt][ks][0] = h1pair(C, ev[2 * mt],     o);
            a2[mt][ks][1] = h1pair(C, ev[2 * mt + 1], o);
            a2[mt][ks][2] = h1pair(C, ev[2 * mt],     o + 8);
            a2[mt][ks][3] = h1pair(C, ev[2 * mt + 1], o + 8);
        }

    // ---- L2: C-fragments become A3-fragments (no smem round trip) ----
    const uint32_t lB = (uint32_t)(l & 7) * 144 + (uint32_t)(l >> 3) * 16;
    uint32_t a3[2][8][4];
    {
        const __half2 z2 = __float2half2_rn(0.f);
        #pragma unroll
        for (int nt = 0; nt < 16; ++nt) {
            uint32_t c[2][2] = {{0u, 0u}, {0u, 0u}};
            #pragma unroll
            for (int kp = 0; kp < 2; ++kp) {
                uint32_t b4[4];
                ldsm4(b4[0], b4[1], b4[2], b4[3],
                      S + SM_WB2 + (uint32_t)(nt * 8) * 144 + lB + kp * 64);
                #pragma unroll
                for (int mt = 0; mt < 2; ++mt) {
                    mma16816h(c[mt], a2[mt][2 * kp],     b4[0], b4[1]);
                    mma16816h(c[mt], a2[mt][2 * kp + 1], b4[2], b4[3]);
                }
            }
            int colb = nt * 8 + 2 * (l & 3);
            __half2 bia = __floats2half2_rn(C[256 + colb], C[256 + colb + 1]);
            #pragma unroll
            for (int mt = 0; mt < 2; ++mt) {
                __half2 v0 = __hmax2(__hadd2(*(__half2*)&c[mt][0], bia), z2);
                __half2 v1 = __hmax2(__hadd2(*(__half2*)&c[mt][1], bia), z2);
                a3[mt][nt >> 1][(nt & 1) * 2 + 0] = *(uint32_t*)&v0;
                a3[mt][nt >> 1][(nt & 1) * 2 + 1] = *(uint32_t*)&v1;
            }
        }
    }

    // ---- L3: 8 chunks x 128 cols; deferred-by-2 epilogue reductions ----
    const uint32_t lB2 = (uint32_t)(l & 7) * 272 + (uint32_t)(l >> 3) * 16;
    uint32_t* cmaxu = (uint32_t*)(sm + SM_CMAX);
    for (int ch = 0; ch < 8; ++ch) {
        cpwait1();
        __syncthreads();
        const uint32_t Wb = S + ((ch & 1) ? SM_WB1 : SM_WB0);
        for (int qq = 0; qq < 8; qq += 2) {
            uint32_t mxr[2][2];     // [sub][n] register partial maxes
            #pragma unroll
            for (int s = 0; s < 2; ++s) {
                int pair = (qq + s + w) & 7;
                int nt0 = pair * 2;
                uint32_t bb[2][4][4];
                #pragma unroll
                for (int n = 0; n < 2; ++n)
                    #pragma unroll
                    for (int kp = 0; kp < 4; ++kp)
                        ldsm4(bb[n][kp][0], bb[n][kp][1], bb[n][kp][2], bb[n][kp][3],
                              Wb + (uint32_t)((nt0 + n) * 8) * 272 + lB2 + kp * 64);
                uint32_t c[2][2][2] = {};
                #pragma unroll
                for (int kp = 0; kp < 4; ++kp)
                    #pragma unroll
                    for (int n = 0; n < 2; ++n)
                        #pragma unroll
                        for (int mt = 0; mt < 2; ++mt) {
                            mma16816h(c[n][mt], a3[mt][2 * kp],     bb[n][kp][0], bb[n][kp][1]);
                            mma16816h(c[n][mt], a3[mt][2 * kp + 1], bb[n][kp][2], bb[n][kp][3]);
                        }
                #pragma unroll
                for (int n = 0; n < 2; ++n) {
                    __half2 mx = __hmax2(
                        __hmax2(*(__half2*)&c[n][0][0], *(__half2*)&c[n][0][1]),
                        __hmax2(*(__half2*)&c[n][1][0], *(__half2*)&c[n][1][1]));
                    mxr[s][n] = *(uint32_t*)&mx;
                }
            }
            // 4 independent shfl-reduce chains (ILP hides latency)
            #pragma unroll
            for (int s = 0; s < 2; ++s)
                #pragma unroll
                for (int n = 0; n < 2; ++n) {
                    __half2 mx = *(__half2*)&mxr[s][n];
                    #pragma unroll
                    for (int off = 4; off < 32; off <<= 1) {
                        uint32_t o = __shfl_xor_sync(0xffffffffu, *(uint32_t*)&mx, off);
                        mx = __hmax2(mx, *(__half2*)&o);
                    }
                    if (l < 4) {
                        int pair = (qq + s + w) & 7;
                        cmaxu[w * 512 + ch * 64 + (pair * 2 + n) * 4 + l] = *(uint32_t*)&mx;
                    }
                }
        }
        __syncthreads();
        if (ch + 2 < 8) {
            const char* src = (const char*)(d_w3h + (ch + 2) * 128 * 128);
            #pragma unroll
            for (int r = 0; r < 8; ++r) {
                int idx = tid + r * 256;
                int n = idx >> 4, qq2 = idx & 15;
                cpasync16(Wb + n * 272 + qq2 * 16, src + n * 256 + qq2 * 16);
            }
        }
        cpcommit();
    }

    // ---- cross-warp reduce + bias + relu + atomics ----
    #pragma unroll
    for (int r = 0; r < 2; ++r) {
        int ci = tid + r * 256;                // half2 index: cols 2ci, 2ci+1
        uint32_t mu = cmaxu[ci];
        __half2 m = *(__half2*)&mu;
        #pragma unroll
        for (int ww = 1; ww < 8; ++ww) {
            uint32_t o = cmaxu[ww * 512 + ci];
            m = __hmax2(m, *(__half2*)&o);
        }
        float2 f = __half22float2(m);
        int col = 2 * ci;
        float v0 = fmaxf(f.x + __ldg(&b3[col]),     0.f);
        float v1 = fmaxf(f.y + __ldg(&b3[col + 1]), 0.f);
        atomicMax((int*)&d_g[b * 1024 + col],     __float_as_int(v0));
        atomicMax((int*)&d_g[b * 1024 + col + 1], __float_as_int(v1));
    }
}

// ---------------- FC head ---------------------------------------------------
// grid = BB * 16; each warp owns 4 outputs -> 2x MLP vs the 12.9us version
__global__ void __launch_bounds__(256) head1_kernel(
    const float* __restrict__ fw1, const float* __restrict__ fb1) {
    __shared__ float gs[1024];
    int b = blockIdx.x >> 4, part = blockIdx.x & 15;
    int tid = threadIdx.x, w = tid >> 5, l = tid & 31;
    for (int v = tid; v < 1024; v += 256) gs[v] = d_g[b * 1024 + v];
    __syncthreads();
    const float4* gr = (const float4*)gs;
    for (int s = 0; s < 4; ++s) {
        int o = part * 32 + w * 4 + s;
        const float4* wr = (const float4*)(fw1 + o * 1024);
        float acc = 0.f;
        #pragma unroll
        for (int q = 0; q < 8; ++q) {
            float4 a = wr[l + q * 32], g4 = gr[l + q * 32];
            acc += a.x * g4.x + a.y * g4.y + a.z * g4.z + a.w * g4.w;
        }
        #pragma unroll
        for (int off = 16; off; off >>= 1) acc += __shfl_xor_sync(0xffffffffu, acc, off);
        if (l == 0) d_f1[b * 512 + o] = fmaxf(acc + fb1[o], 0.f);
    }
}

__global__ void __launch_bounds__(256) head2_kernel(
    const float* __restrict__ fw2, const float* __restrict__ fb2,
    const float* __restrict__ fw3, const float* __restrict__ fb3) {
    __shared__ float f1s[512], f2s[256];
    int b = blockIdx.x, tid = threadIdx.x, w = tid >> 5, l = tid & 31;
    for (int v = tid; v < 512; v += 256) f1s[v] = d_f1[b * 512 + v];
    __syncthreads();
    const float4* f1r = (const float4*)f1s;
    for (int s = 0; s < 32; ++s) {
        int o = w * 32 + s;
        const float4* wr = (const float4*)(fw2 + o * 512);
        float acc = 0.f;
        #pragma unroll
        for (int q = 0; q < 4; ++q) {
            float4 a = wr[l + q * 32], g4 = f1r[l + q * 32];
            acc += a.x * g4.x + a.y * g4.y + a.z * g4.z + a.w * g4.w;
        }
        #pragma unroll
        for (int off = 16; off; off >>= 1) acc += __shfl_xor_sync(0xffffffffu, acc, off);
        if (l == 0) f2s[o] = fmaxf(acc + fb2[o], 0.f);
    }
    __syncthreads();
    const float4* f2r = (const float4*)f2s;
    for (int o = w; o < 9; o += 8) {
        const float4* wr = (const float4*)(fw3 + o * 256);
        float acc = 0.f;
        #pragma unroll
        for (int q = 0; q < 2; ++q) {
            float4 a = wr[l + q * 32], g4 = f2r[l + q * 32];
            acc += a.x * g4.x + a.y * g4.y + a.z * g4.z + a.w * g4.w;
        }
        #pragma unroll
        for (int off = 16; off; off >>= 1) acc += __shfl_xor_sync(0xffffffffu, acc, off);
        if (l == 0) {
            float s = acc + fb3[o];
            if (o == 0 || o == 4 || o == 8) s += 1.f;
            d_tm[b * 9 + o] = s;
        }
    }
}

// ---------------- out = bmm(x^T, t)^T --------------------------------------
__global__ void final_kernel(const float* __restrict__ x, float* __restrict__ out) {
    int id = blockIdx.x * blockDim.x + threadIdx.x;
    int b = id >> 12, n = id & (NN - 1);
    const float* xb = x + (size_t)b * 3 * NN;
    float a0 = xb[n], a1 = xb[NN + n], a2 = xb[2 * NN + n];
    const float* t = d_tm + b * 9;
    float* ob = out + (size_t)b * 3 * NN;
    ob[n]          = a0 * t[0] + a1 * t[3] + a2 * t[6];
    ob[NN + n]     = a0 * t[1] + a1 * t[4] + a2 * t[7];
    ob[2 * NN + n] = a0 * t[2] + a1 * t[5] + a2 * t[8];
}

extern "C" void kernel_launch(void* const* d_in, const int* in_sizes, int n_in,
                              void* d_out, int out_size) {
    const float* x   = (const float*)d_in[0];
    const float* w1  = (const float*)d_in[1];
    const float* b1  = (const float*)d_in[2];
    const float* w2  = (const float*)d_in[3];
    const float* b2  = (const float*)d_in[4];
    const float* w3  = (const float*)d_in[5];
    const float* b3  = (const float*)d_in[6];
    const float* fw1 = (const float*)d_in[7];
    const float* fb1 = (const float*)d_in[8];
    const float* fw2 = (const float*)d_in[9];
    const float* fb2 = (const float*)d_in[10];
    const float* fw3 = (const float*)d_in[11];
    const float* fb3 = (const float*)d_in[12];
    float* out = (float*)d_out;

    cudaFuncSetAttribute(edge_mlp_kernel,
                         cudaFuncAttributeMaxDynamicSharedMemorySize, SM_TOT);

    prep_all_kernel<<<512, 256>>>(x, w2, w3);          // idx 0 (merged prep)
    knn_kernel<<<BB * NN / 16, 256>>>();               // idx 1 (2 points/warp)
    edge_mlp_kernel<<<BB * NN / 8, 256, SM_TOT>>>(w1, b1, b2, b3);  // idx 2
    head1_kernel<<<BB * 16, 256>>>(fw1, fb1);          // idx 3 (2x parallelism)
    head2_kernel<<<BB, 256>>>(fw2, fb2, fw3, fb3);     // idx 4
    final_kernel<<<BB * NN / 256, 256>>>(x, out);      // idx 5
}